// round 1
// baseline (speedup 1.0000x reference)
#include <cuda_runtime.h>

// Ende_3332894622093: B=65536, D=40, HB=20.
// out   = [t1 | s2]                 (B,1,40)
// J_T   = [[diag(e4)+JJ12@J21, JJ12*e2],
//          [J21,               diag(e2)]]   (B,40,40)
// d_out layout assumed: out flattened (n*40) followed by J_T flattened (n*1600).

#define NW 8  // warps (=batch items) per block

struct WarpSmem {
    float  xs[40];     // input row
    float2 bb[20];     // (b1, b2) per k
    float  s2s[20];    // s2 vector
    float  jjs[400];   // JJ12, row-major stride 20
};

__global__ __launch_bounds__(NW * 32)
void ende_kernel(const float* __restrict__ src,
                 const float* __restrict__ w1,
                 const float* __restrict__ w2,
                 const float* __restrict__ w3,
                 const float* __restrict__ w4,
                 float* __restrict__ outp,
                 float* __restrict__ jt,
                 int n)
{
    __shared__ float w1s[400], w2s[400], w3s[400], w4s[400];
    __shared__ WarpSmem ws[NW];

    const int tid = threadIdx.x;
    for (int i = tid; i < 400; i += NW * 32) {
        w1s[i] = w1[i];
        w2s[i] = w2[i];
        w3s[i] = w3[i];
        w4s[i] = w4[i];
    }
    __syncthreads();

    const int warp = tid >> 5;
    const int lane = tid & 31;
    const int b = blockIdx.x * NW + warp;
    if (b >= n) return;

    WarpSmem& S = ws[warp];

    // ---- load x (40 floats = 10 float4) ----
    const float4* xg = (const float4*)(src + (size_t)b * 40);
    if (lane < 10) ((float4*)S.xs)[lane] = xg[lane];
    __syncwarp();

    const int j = lane;
    float e2j = 0.f, e4j = 0.f, t1j = 0.f, s2j = 0.f;

    // ---- phase 2: f1, f2, e2, b1, b2, s2 ----
    if (j < 20) {
        float acc1 = 0.f, acc2 = 0.f;
        const float4* xv  = (const float4*)S.xs;          // p1 broadcast
        const float4* w1r = (const float4*)&w1s[j * 20];
        const float4* w2r = (const float4*)&w2s[j * 20];
        #pragma unroll
        for (int k4 = 0; k4 < 5; k4++) {
            float4 xx = xv[k4], a = w1r[k4], c = w2r[k4];
            acc1 += xx.x * a.x + xx.y * a.y + xx.z * a.z + xx.w * a.w;
            acc2 += xx.x * c.x + xx.y * c.y + xx.z * c.z + xx.w * c.w;
        }
        float f1 = tanhf(acc1);
        float f2 = tanhf(acc2);
        e2j = expf(f2);
        float p2  = S.xs[20 + j];
        float p2e = p2 * e2j;
        s2j = p2e + f1;
        S.bb[j]  = make_float2(1.f - f1 * f1, p2e * (1.f - f2 * f2));
        S.s2s[j] = s2j;
    }
    __syncwarp();

    // ---- phase 3: f3, f4, e4, t1, JJ12 row j ----
    if (j < 20) {
        float acc3 = 0.f, acc4 = 0.f;
        const float4* sv  = (const float4*)S.s2s;         // s2 broadcast
        const float4* w3r = (const float4*)&w3s[j * 20];
        const float4* w4r = (const float4*)&w4s[j * 20];
        #pragma unroll
        for (int k4 = 0; k4 < 5; k4++) {
            float4 xx = sv[k4], a = w3r[k4], c = w4r[k4];
            acc3 += xx.x * a.x + xx.y * a.y + xx.z * a.z + xx.w * a.w;
            acc4 += xx.x * c.x + xx.y * c.y + xx.z * c.z + xx.w * c.w;
        }
        float f3 = tanhf(acc3);
        float f4 = tanhf(acc4);
        e4j = expf(f4);
        float s1  = S.xs[j];
        float s1e = s1 * e4j;
        t1j = s1e + f3;
        float a3 = 1.f - f3 * f3;
        float a4 = s1e * (1.f - f4 * f4);
        float4* jj = (float4*)&S.jjs[j * 20];
        #pragma unroll
        for (int k4 = 0; k4 < 5; k4++) {
            float4 a_ = w3r[k4], c_ = w4r[k4], r;
            r.x = a3 * a_.x + a4 * c_.x;
            r.y = a3 * a_.y + a4 * c_.y;
            r.z = a3 * a_.z + a4 * c_.z;
            r.w = a3 * a_.w + a4 * c_.w;
            jj[k4] = r;
        }
    }
    __syncwarp();

    // ---- phase 4: J21 column j (registers), bottom half writes, matmul top half ----
    float* J = jt   + (size_t)b * 1600;
    float* O = outp + (size_t)b * 40;

    if (j < 20) {
        O[j]      = t1j;
        O[20 + j] = s2j;

        float my_col[20];
        #pragma unroll
        for (int k = 0; k < 20; k++) {
            float2 bv = S.bb[k];                    // broadcast LDS.64
            float c = bv.x * w1s[k * 20 + j] + bv.y * w2s[k * 20 + j];
            my_col[k] = c;
            J[(20 + k) * 40 + j]      = c;                        // BL = J21
            J[(20 + k) * 40 + 20 + j] = (k == j) ? e2j : 0.f;     // BR = diag(e2)
        }

        for (int i = 0; i < 20; i++) {
            const float4* jj = (const float4*)&S.jjs[i * 20];     // broadcast LDS.128
            float acc = 0.f;
            #pragma unroll
            for (int k4 = 0; k4 < 5; k4++) {
                float4 v = jj[k4];
                acc += v.x * my_col[4 * k4 + 0] + v.y * my_col[4 * k4 + 1]
                     + v.z * my_col[4 * k4 + 2] + v.w * my_col[4 * k4 + 3];
            }
            if (i == j) acc += e4j;
            J[i * 40 + j]      = acc;                             // TL
            J[i * 40 + 20 + j] = S.jjs[i * 20 + j] * e2j;         // TR
        }
    }
}

extern "C" void kernel_launch(void* const* d_in, const int* in_sizes, int n_in,
                              void* d_out, int out_size)
{
    const float* src = (const float*)d_in[0];
    const float* w1  = (const float*)d_in[1];
    const float* w2  = (const float*)d_in[2];
    const float* w3  = (const float*)d_in[3];
    const float* w4  = (const float*)d_in[4];

    int n = in_sizes[0] / 40;
    float* outp = (float*)d_out;
    float* jt   = (float*)d_out + (size_t)n * 40;

    int blocks = (n + NW - 1) / NW;
    ende_kernel<<<blocks, NW * 32>>>(src, w1, w2, w3, w4, outp, jt, n);
}